// round 4
// baseline (speedup 1.0000x reference)
#include <cuda_runtime.h>

#define NB_DIMS 128
#define BATCH   16384
#define S       4            // samples per warp

// Each warp processes S=4 samples. All 2*S row gathers are issued as
// independent LDG.128s before any use, maximizing per-warp MLP.
__global__ void __launch_bounds__(256) sgns_dot_kernel(
    const int*   __restrict__ vii,   // [BATCH, 2] int32
    const float* __restrict__ W,     // [NB_VECS, 128] f32
    float*       __restrict__ out)   // [BATCH] f32
{
    int gtid = blockIdx.x * blockDim.x + threadIdx.x;
    int warp = gtid >> 5;
    int lane = gtid & 31;
    int base = warp * S;             // first sample of this warp
    if (base >= BATCH) return;

    // Lanes 0..S-1 fetch one int2 index pair each; broadcast to all lanes.
    int2 my = make_int2(0, 0);
    if (lane < S)
        my = __ldg(reinterpret_cast<const int2*>(vii) + base + lane);

    int i0[S], i1[S];
    #pragma unroll
    for (int k = 0; k < S; k++) {
        i0[k] = __shfl_sync(0xffffffffu, my.x, k);
        i1[k] = __shfl_sync(0xffffffffu, my.y, k);
    }

    // Issue all 2*S independent 16B gathers before consuming any.
    float4 a[S], b[S];
    #pragma unroll
    for (int k = 0; k < S; k++) {
        a[k] = __ldg(reinterpret_cast<const float4*>(
                         W + (long long)i0[k] * NB_DIMS) + lane);
        b[k] = __ldg(reinterpret_cast<const float4*>(
                         W + (long long)i1[k] * NB_DIMS) + lane);
    }

    float s[S];
    #pragma unroll
    for (int k = 0; k < S; k++)
        s[k] = a[k].x * b[k].x + a[k].y * b[k].y
             + a[k].z * b[k].z + a[k].w * b[k].w;

    // S independent warp reductions (shuffles pipeline across k).
    #pragma unroll
    for (int o = 16; o > 0; o >>= 1) {
        #pragma unroll
        for (int k = 0; k < S; k++)
            s[k] += __shfl_xor_sync(0xffffffffu, s[k], o);
    }

    if (lane < S)
        out[base + lane] = s[lane];
}

extern "C" void kernel_launch(void* const* d_in, const int* in_sizes, int n_in,
                              void* d_out, int out_size)
{
    const void* p0 = d_in[0];
    const void* p1 = d_in[1];
    const int*   vii;
    const float* W;
    if (in_sizes[0] < in_sizes[1]) {
        vii = (const int*)p0;  W = (const float*)p1;
    } else {
        vii = (const int*)p1;  W = (const float*)p0;
    }
    float* out = (float*)d_out;

    const int threads = 256;                             // 8 warps/block
    const int samples_per_block = (threads / 32) * S;    // 32
    const int blocks = (BATCH + samples_per_block - 1) / samples_per_block; // 512
    sgns_dot_kernel<<<blocks, threads>>>(vii, W, out);
}

// round 5
// speedup vs baseline: 1.3023x; 1.3023x over previous
#include <cuda_runtime.h>

#define NB_DIMS 128
#define BATCH   16384
#define S       2            // samples per warp

// Each warp handles 2 samples. All 4 indices arrive in ONE broadcast int4 load
// (no shuffles, no predication), then 4 independent LDG.128 gathers issue
// back-to-back. Keeps warp count high (8192) while doubling per-warp MLP.
__global__ void __launch_bounds__(256) sgns_dot_kernel(
    const int*   __restrict__ vii,   // [BATCH, 2] int32
    const float* __restrict__ W,     // [NB_VECS, 128] f32
    float*       __restrict__ out)   // [BATCH] f32
{
    int gtid = blockIdx.x * blockDim.x + threadIdx.x;
    int warp = gtid >> 5;
    int lane = gtid & 31;
    int base = warp * S;
    if (base >= BATCH) return;

    // One uniform 16B load: indices for both samples (i0,i1 of s0; i0,i1 of s1).
    int4 q = __ldg(reinterpret_cast<const int4*>(vii) + warp);

    const float4* __restrict__ a0p =
        reinterpret_cast<const float4*>(W + (long long)q.x * NB_DIMS);
    const float4* __restrict__ b0p =
        reinterpret_cast<const float4*>(W + (long long)q.y * NB_DIMS);
    const float4* __restrict__ a1p =
        reinterpret_cast<const float4*>(W + (long long)q.z * NB_DIMS);
    const float4* __restrict__ b1p =
        reinterpret_cast<const float4*>(W + (long long)q.w * NB_DIMS);

    // 4 independent 16B gathers, all issued before any consumption.
    float4 a0 = __ldg(a0p + lane);
    float4 b0 = __ldg(b0p + lane);
    float4 a1 = __ldg(a1p + lane);
    float4 b1 = __ldg(b1p + lane);

    float s0 = a0.x * b0.x + a0.y * b0.y + a0.z * b0.z + a0.w * b0.w;
    float s1 = a1.x * b1.x + a1.y * b1.y + a1.z * b1.z + a1.w * b1.w;

    #pragma unroll
    for (int o = 16; o > 0; o >>= 1) {
        s0 += __shfl_xor_sync(0xffffffffu, s0, o);
        s1 += __shfl_xor_sync(0xffffffffu, s1, o);
    }

    if (lane == 0) {
        // float2 store: both results, one STG.64.
        *reinterpret_cast<float2*>(out + base) = make_float2(s0, s1);
    }
}

extern "C" void kernel_launch(void* const* d_in, const int* in_sizes, int n_in,
                              void* d_out, int out_size)
{
    const void* p0 = d_in[0];
    const void* p1 = d_in[1];
    const int*   vii;
    const float* W;
    if (in_sizes[0] < in_sizes[1]) {
        vii = (const int*)p0;  W = (const float*)p1;
    } else {
        vii = (const int*)p1;  W = (const float*)p0;
    }
    float* out = (float*)d_out;

    const int threads = 256;                             // 8 warps/block
    const int samples_per_block = (threads / 32) * S;    // 16
    const int blocks = (BATCH + samples_per_block - 1) / samples_per_block; // 1024
    sgns_dot_kernel<<<blocks, threads>>>(vii, W, out);
}